// round 8
// baseline (speedup 1.0000x reference)
#include <cuda_runtime.h>
#include <math.h>
#include <stdint.h>

// Problem sizes (fixed by the reference)
#define BB 8
#define LL 2048
#define DD 512
#define MT (BB*LL)          // 16384 rows
#define SZ ((long long)MT*DD)

// ---------------- scratch (device globals; no allocation allowed) ----------------
__device__ float g_xc[MT*DD];        // conv output (fp32 row-major logical, aux for EPI2)
__device__ float g_xct[MT*DD];       // conv output, tf32, sigma-col-interleaved
__device__ float g_h1[2*MT*DD];      // tf32 gelu(..), sigma-interleaved
__device__ float g_q[MT*DD];         // normalized q (fp32 row-major logical, aux for EPI4)
__device__ float g_qt[MT*DD];        // normalized q, tf32, sigma-interleaved
__device__ float g_hm[MT*DD];        // raw q-gemm out (row-major) then gelu-stage1 (sigma)
__device__ float g_accum[MT + 2*LL]; // [0:MT) hs rowsums, [MT:MT+LL) eta sum, [MT+LL:) alpha sum
__device__ float g_ps[2*LL];         // [0:LL) p,  [LL:2LL) s
__device__ float g_qsum[MT];         // rowsum of q
__device__ float g_wt[7*DD*DD];      // transposed tf32 weights, sigma-interleaved k

__device__ __forceinline__ float gelu_exact(float x) {
    return 0.5f * x * (1.0f + erff(x * 0.70710678118654752f));
}
__device__ __forceinline__ float sigm(float x) {
    return 1.0f / (1.0f + expf(-x));
}
__device__ __forceinline__ uint32_t tf32_bits(float x) {
    uint32_t u; asm("cvt.rna.tf32.f32 %0, %1;" : "=r"(u) : "f"(x)); return u;
}
__device__ __forceinline__ float tf32_round(float x) {
    return __uint_as_float(tf32_bits(x));
}
__device__ __forceinline__ uint32_t smem_u32(const void* p) {
    uint32_t a;
    asm("{ .reg .u64 t; cvta.to.shared.u64 t, %1; cvt.u32.u64 %0, t; }" : "=r"(a) : "l"(p));
    return a;
}
// within-8-group column interleave: logical k -> physical position
__device__ __forceinline__ int sigk(int k) {
    return (k & ~7) | ((k & 3) << 1) | ((k >> 2) & 1);
}

// ---------------- zero accumulators ----------------
__global__ void zero_kernel(float* a, int n) {
    int i = blockIdx.x * blockDim.x + threadIdx.x;
    if (i < n) a[i] = 0.0f;
}

// ---------------- prep weights: transpose (or copy) + tf32 + sigma cols -----------
// slots: 0 eta_w1^T, 1 alpha_w1^T, 2 eta_w2^T, 3 alpha_w2^T, 4 q_w (copy), 5 mem_w1^T, 6 mem_w2^T
// Output: Bt[n][sigk(k)] row-major, 512/row.
__global__ void prep_weights(const float* __restrict__ ew1, const float* __restrict__ aw1,
                             const float* __restrict__ ew2, const float* __restrict__ aw2,
                             const float* __restrict__ qw,  const float* __restrict__ mw1,
                             const float* __restrict__ mw2, float* __restrict__ wt) {
    __shared__ float tile[32][33];
    int zi = blockIdx.z;
    const float* src; bool tr = true;
    switch (zi) {
        case 0: src = ew1; break;
        case 1: src = aw1; break;
        case 2: src = ew2; break;
        case 3: src = aw2; break;
        case 4: src = qw; tr = false; break;
        case 5: src = mw1; break;
        default: src = mw2; break;
    }
    float* dst = wt + (long long)zi * DD * DD;
    int bx = blockIdx.x * 32, by = blockIdx.y * 32;
    int tx = threadIdx.x, ty = threadIdx.y;  // (32, 8)
    if (tr) {
        #pragma unroll
        for (int i = 0; i < 32; i += 8)
            tile[ty + i][tx] = src[(long long)(by + ty + i) * DD + bx + tx];
        __syncthreads();
        #pragma unroll
        for (int i = 0; i < 32; i += 8)
            dst[(long long)(bx + ty + i) * DD + sigk(by + tx)] = tf32_round(tile[tx][ty + i]);
    } else {
        #pragma unroll
        for (int i = 0; i < 32; i += 8)
            dst[(long long)(by + ty + i) * DD + sigk(bx + tx)] =
                tf32_round(src[(long long)(by + ty + i) * DD + bx + tx]);
    }
}

// ---------------- causal depthwise conv (k=4, left pad 3) + bias ----------------
__global__ void conv_kernel(const float* __restrict__ x, const float* __restrict__ w,
                            const float* __restrict__ bias, float* __restrict__ xc,
                            float* __restrict__ xct) {
    int idx = blockIdx.x * blockDim.x + threadIdx.x;
    if (idx >= MT * (DD/4)) return;
    int d4 = idx & 127;
    int r  = idx >> 7;
    int l  = r & (LL-1);
    int d  = d4 * 4;
    float4 out = *(const float4*)(bias + d);
    #pragma unroll
    for (int k = 0; k < 4; k++) {
        int li = l + k - 3;
        if (li >= 0) {
            float4 xv = *(const float4*)(x + (long long)(r + k - 3) * DD + d);
            out.x += xv.x * w[(d+0)*4 + k];
            out.y += xv.y * w[(d+1)*4 + k];
            out.z += xv.z * w[(d+2)*4 + k];
            out.w += xv.w * w[(d+3)*4 + k];
        }
    }
    long long ro = (long long)r * DD;
    *(float4*)(xc + ro + d) = out;
    // sigma positions for d..d+3 (d%4==0): base + {0,2,4,6}
    int b8 = (d & ~7) | ((d >> 2) & 1);
    xct[ro + b8    ] = tf32_round(out.x);
    xct[ro + b8 + 2] = tf32_round(out.y);
    xct[ro + b8 + 4] = tf32_round(out.z);
    xct[ro + b8 + 6] = tf32_round(out.w);
}

// ---------------- l2norm rows + rowsum (fp32 q logical + tf32 sigma copy) ----------
__global__ void l2norm_kernel(const float* __restrict__ G, float* __restrict__ q,
                              float* __restrict__ qt, float* __restrict__ qsum) {
    int r = blockIdx.x;
    int t = threadIdx.x;
    float4 v = ((const float4*)(G + (long long)r * DD))[t];
    float ss = v.x*v.x + v.y*v.y + v.z*v.z + v.w*v.w;
    float sg = v.x + v.y + v.z + v.w;
    #pragma unroll
    for (int o = 16; o > 0; o >>= 1) {
        ss += __shfl_down_sync(0xffffffffu, ss, o);
        sg += __shfl_down_sync(0xffffffffu, sg, o);
    }
    __shared__ float sh_ss[4], sh_sg[4], sh_scale;
    int w = t >> 5;
    if ((t & 31) == 0) { sh_ss[w] = ss; sh_sg[w] = sg; }
    __syncthreads();
    if (t == 0) {
        float S = sh_ss[0] + sh_ss[1] + sh_ss[2] + sh_ss[3];
        float Gs = sh_sg[0] + sh_sg[1] + sh_sg[2] + sh_sg[3];
        float scale = 1.0f / fmaxf(sqrtf(S), 1e-12f);
        sh_scale = scale;
        qsum[r] = Gs * scale;
    }
    __syncthreads();
    float sc = sh_scale;
    float4 o4 = { v.x*sc, v.y*sc, v.z*sc, v.w*sc };
    long long ro = (long long)r * DD;
    *(float4*)(q + ro + t * 4) = o4;
    int d = t * 4;
    int b8 = (d & ~7) | ((d >> 2) & 1);
    qt[ro + b8    ] = tf32_round(o4.x);
    qt[ro + b8 + 2] = tf32_round(o4.y);
    qt[ro + b8 + 4] = tf32_round(o4.z);
    qt[ro + b8 + 6] = tf32_round(o4.w);
}

// ---------------- parallel affine scan for p_t, s_t ----------------
__global__ void scan_kernel(const float* __restrict__ red, float* __restrict__ PS) {
    __shared__ float Aa[2][LL];
    __shared__ float Bb[2][LL];
    const float inv = 1.0f / (float)(BB * DD);
    int t = threadIdx.x;  // 1024
    #pragma unroll
    for (int h = 0; h < 2; h++) {
        int e = t + h * 1024;
        Aa[0][e] = red[LL + e] * inv;        // alpha mean
        Bb[0][e] = -0.01f * red[e] * inv;    // -0.01 * eta mean
    }
    int cur = 0;
    for (int d = 1; d < LL; d <<= 1) {
        __syncthreads();
        #pragma unroll
        for (int h = 0; h < 2; h++) {
            int e = t + h * 1024;
            float A2 = Aa[cur][e], B2 = Bb[cur][e];
            if (e >= d) {
                float A1 = Aa[cur][e - d], B1 = Bb[cur][e - d];
                B2 = A2 * B1 + B2;
                A2 = A1 * A2;
            }
            Aa[cur ^ 1][e] = A2;
            Bb[cur ^ 1][e] = B2;
        }
        cur ^= 1;
    }
    __syncthreads();
    #pragma unroll
    for (int h = 0; h < 2; h++) {
        int e = t + h * 1024;
        PS[e]      = (e == 0) ? 1.0f : Aa[cur][e - 1];
        PS[LL + e] = (e == 0) ? 0.0f : Bb[cur][e - 1];
    }
}

// ---------------- tf32 mma.sync GEMM, sigma-interleaved cols, LDS.64 frags ---------
// A (MT x 512 sigma), Bt (512 x 512 sigma-k, row n). CTA 128x128, BK=32, 8 warps 64x32.
// Smem stage: 128 rows x 40 words (32 data + 8 pad) -> conflict-free LDS.64.
// EPI 0: C(f32 rowmajor logical) = acc
// EPI 1: C(tf32 sigma) = gelu(acc)
// EPI 2: no store; atomicAdd red[(r&2047)] += sum_cols sigmoid(aux[r,c]+acc)
// EPI 3: h = gelu(P[l]*acc + S[l]*vin[r]); C(tf32 sigma) = h; atomicAdd red0[r] += sum h
// EPI 4: C(f32 rowmajor logical) = aux[r,c] + P[l]*acc + S[l]*vin[r]
#define SWW 40
#define STG_BYTES (128*SWW*4)           // 20480 per matrix-stage
#define SMEM_GB (4 * STG_BYTES)         // 2 stages x (A+B) = 81920 B

template<int EPI>
__global__ __launch_bounds__(256, 2)
void gemm_mma(const float* __restrict__ A, long long Astride,
              const float* __restrict__ B0, const float* __restrict__ B1,
              float* C0, float* C1,
              const float* __restrict__ aux,
              const float* __restrict__ P, const float* __restrict__ S,
              const float* __restrict__ vin,
              float* red0, float* red1) {
    extern __shared__ char smemBuf[];
    const uint32_t sbase = smem_u32(smemBuf);

    const int tid  = threadIdx.x;
    const int lane = tid & 31, warp = tid >> 5;
    const int wm = warp >> 2, wn = warp & 3;       // 2 x 4 warp grid, warp tile 64x32
    const int qr = lane >> 2, qk = lane & 3;
    const int rowBase = blockIdx.y * 128;
    const int colBase = blockIdx.x * 128;
    const int z = blockIdx.z;
    const float* Ab = A + (long long)z * Astride;
    const float* Bt = z ? B1 : B0;
    float* C        = z ? C1 : C0;

    float acc[4][4][4];
    #pragma unroll
    for (int mf = 0; mf < 4; mf++)
        #pragma unroll
        for (int nf = 0; nf < 4; nf++)
            #pragma unroll
            for (int i = 0; i < 4; i++) acc[mf][nf][i] = 0.0f;

    // cp.async: 128 rows x 8 x 16B per matrix per BK=32 chunk; 4 per thread each.
    auto issue = [&](int kc, int st) {
        const uint32_t abase = sbase + st * STG_BYTES;
        const uint32_t bbase = sbase + (2 + st) * STG_BYTES;
        const int k0 = kc * 32;
        #pragma unroll
        for (int i = 0; i < 4; i++) {
            int li = i * 256 + tid;
            int row = li >> 3, seg = li & 7;
            const float* ga = Ab + (long long)(rowBase + row) * DD + k0 + seg * 4;
            const float* gb = Bt + (long long)(colBase + row) * DD + k0 + seg * 4;
            uint32_t soff = (row * SWW + seg * 4) * 4;
            asm volatile("cp.async.cg.shared.global [%0], [%1], 16;"
                :: "r"(abase + soff), "l"(__cvta_generic_to_global(ga)));
            asm volatile("cp.async.cg.shared.global [%0], [%1], 16;"
                :: "r"(bbase + soff), "l"(__cvta_generic_to_global(gb)));
        }
        asm volatile("cp.async.commit_group;" ::: "memory");
    };

    issue(0, 0);

    for (int kc = 0; kc < 16; kc++) {
        const int s = kc & 1;
        asm volatile("cp.async.wait_group 0;" ::: "memory");
        __syncthreads();
        if (kc < 15) issue(kc + 1, s ^ 1);
        const uint32_t aStg = sbase + s * STG_BYTES;
        const uint32_t bStg = sbase + (2 + s) * STG_BYTES;

        #pragma unroll
        for (int ks = 0; ks < 4; ks++) {
            uint32_t a[4][4], b[4][2];
            #pragma unroll
            for (int mf = 0; mf < 4; mf++) {
                uint32_t lo = aStg + (((wm * 64 + mf * 16 + qr) * SWW) + ks * 8 + 2 * qk) * 4;
                asm volatile("ld.shared.v2.b32 {%0,%1}, [%2];"
                    : "=r"(a[mf][0]), "=r"(a[mf][2]) : "r"(lo));
                asm volatile("ld.shared.v2.b32 {%0,%1}, [%2];"
                    : "=r"(a[mf][1]), "=r"(a[mf][3]) : "r"(lo + 8 * SWW * 4));
            }
            #pragma unroll
            for (int nf = 0; nf < 4; nf++) {
                uint32_t ba = bStg + (((wn * 32 + nf * 8 + qr) * SWW) + ks * 8 + 2 * qk) * 4;
                asm volatile("ld.shared.v2.b32 {%0,%1}, [%2];"
                    : "=r"(b[nf][0]), "=r"(b[nf][1]) : "r"(ba));
            }
            #pragma unroll
            for (int mf = 0; mf < 4; mf++)
                #pragma unroll
                for (int nf = 0; nf < 4; nf++)
                    asm volatile(
                        "mma.sync.aligned.m16n8k8.row.col.f32.tf32.tf32.f32 "
                        "{%0,%1,%2,%3}, {%4,%5,%6,%7}, {%8,%9}, {%0,%1,%2,%3};"
                        : "+f"(acc[mf][nf][0]), "+f"(acc[mf][nf][1]),
                          "+f"(acc[mf][nf][2]), "+f"(acc[mf][nf][3])
                        : "r"(a[mf][0]), "r"(a[mf][1]), "r"(a[mf][2]), "r"(a[mf][3]),
                          "r"(b[nf][0]), "r"(b[nf][1]));
        }
    }

    // ---- epilogue ----
    float* red = (EPI == 2) ? (z ? red1 : red0) : red0;
    const int cBase = colBase + wn * 32 + 2 * qk;

    #pragma unroll
    for (int mf = 0; mf < 4; mf++) {
        #pragma unroll
        for (int half_ = 0; half_ < 2; half_++) {
            int r = rowBase + wm * 64 + mf * 16 + qr + half_ * 8;
            int l = r & (LL - 1);
            int ci = half_ * 2;
            float part = 0.0f;
            float pl = 0.f, sl = 0.f, vv = 0.f;
            if (EPI == 3 || EPI == 4) { pl = P[l]; sl = S[l]; vv = vin[r]; }
            long long ro = (long long)r * DD;

            #pragma unroll
            for (int nf = 0; nf < 4; nf++) {
                float v0 = acc[mf][nf][ci], v1 = acc[mf][nf][ci + 1];
                int c0 = cBase + nf * 8;   // logical col (c0&3 in {0,2})
                if (EPI == 0) {
                    float2 o = { v0, v1 };
                    *(float2*)(C + ro + c0) = o;
                } else if (EPI == 1) {
                    int sc = (c0 & ~7) | ((c0 & 3) << 1) | ((c0 >> 2) & 1);
                    C[ro + sc]     = tf32_round(gelu_exact(v0));
                    C[ro + sc + 2] = tf32_round(gelu_exact(v1));
                } else if (EPI == 2) {
                    float2 a2 = *(const float2*)(aux + ro + c0);
                    part += sigm(a2.x + v0) + sigm(a2.y + v1);
                } else if (EPI == 3) {
                    float h0 = gelu_exact(pl * v0 + sl * vv);
                    float h1 = gelu_exact(pl * v1 + sl * vv);
                    part += h0 + h1;
                    int sc = (c0 & ~7) | ((c0 & 3) << 1) | ((c0 >> 2) & 1);
                    C[ro + sc]     = tf32_round(h0);
                    C[ro + sc + 2] = tf32_round(h1);
                } else if (EPI == 4) {
                    float2 a2 = *(const float2*)(aux + ro + c0);
                    float2 o = { a2.x + pl * v0 + sl * vv,
                                 a2.y + pl * v1 + sl * vv };
                    *(float2*)(C + ro + c0) = o;
                }
            }
            if (EPI == 2 || EPI == 3) {
                part += __shfl_xor_sync(0xffffffffu, part, 1);
                part += __shfl_xor_sync(0xffffffffu, part, 2);
                if (qk == 0) {
                    if (EPI == 2) atomicAdd(&red[l], part);
                    else          atomicAdd(&red[r], part);
                }
            }
        }
    }
}

// ---------------- launcher ----------------
extern "C" void kernel_launch(void* const* d_in, const int* in_sizes, int n_in,
                              void* d_out, int out_size) {
    const float* x        = (const float*)d_in[0];
    const float* conv_w   = (const float*)d_in[1];
    const float* conv_b   = (const float*)d_in[2];
    const float* q_w      = (const float*)d_in[3];
    const float* mem_w1   = (const float*)d_in[4];
    const float* mem_w2   = (const float*)d_in[5];
    const float* eta_w1   = (const float*)d_in[6];
    const float* eta_w2   = (const float*)d_in[7];
    const float* alpha_w1 = (const float*)d_in[8];
    const float* alpha_w2 = (const float*)d_in[9];
    float* out = (float*)d_out;

    float *xc, *xct, *h1, *qb, *qt, *hm, *accum, *ps, *qsum, *wt;
    cudaGetSymbolAddress((void**)&xc,    g_xc);
    cudaGetSymbolAddress((void**)&xct,   g_xct);
    cudaGetSymbolAddress((void**)&h1,    g_h1);
    cudaGetSymbolAddress((void**)&qb,    g_q);
    cudaGetSymbolAddress((void**)&qt,    g_qt);
    cudaGetSymbolAddress((void**)&hm,    g_hm);
    cudaGetSymbolAddress((void**)&accum, g_accum);
    cudaGetSymbolAddress((void**)&ps,    g_ps);
    cudaGetSymbolAddress((void**)&qsum,  g_qsum);
    cudaGetSymbolAddress((void**)&wt,    g_wt);

    float* hs        = accum;
    float* eta_sum   = accum + MT;
    float* alpha_sum = accum + MT + LL;
    float* Pp = ps;
    float* Ss = ps + LL;

    static bool attr_done = false;
    if (!attr_done) {
        cudaFuncSetAttribute(gemm_mma<0>, cudaFuncAttributeMaxDynamicSharedMemorySize, SMEM_GB);
        cudaFuncSetAttribute(gemm_mma<1>, cudaFuncAttributeMaxDynamicSharedMemorySize, SMEM_GB);
        cudaFuncSetAttribute(gemm_mma<2>, cudaFuncAttributeMaxDynamicSharedMemorySize, SMEM_GB);
        cudaFuncSetAttribute(gemm_mma<3>, cudaFuncAttributeMaxDynamicSharedMemorySize, SMEM_GB);
        cudaFuncSetAttribute(gemm_mma<4>, cudaFuncAttributeMaxDynamicSharedMemorySize, SMEM_GB);
        attr_done = true;
    }

    // 0) zero atomic accumulators
    {
        int n = MT + 2 * LL;
        zero_kernel<<<(n + 255) / 256, 256>>>(accum, n);
    }
    // 0b) weights -> transposed + tf32 + sigma cols
    prep_weights<<<dim3(16, 16, 7), dim3(32, 8)>>>(eta_w1, alpha_w1, eta_w2, alpha_w2,
                                                   q_w, mem_w1, mem_w2, wt);
    // 1) conv (fp32 xc logical + tf32 xct sigma)
    conv_kernel<<<(MT * (DD/4) + 255) / 256, 256>>>(x, conv_w, conv_b, xc, xct);

    dim3 grid2(DD / 128, MT / 128, 2);
    dim3 grid1(DD / 128, MT / 128, 1);
    float* wt0 = wt + 0LL * DD * DD;  // eta_w1^T
    float* wt1 = wt + 1LL * DD * DD;  // alpha_w1^T
    float* wt2 = wt + 2LL * DD * DD;  // eta_w2^T
    float* wt3 = wt + 3LL * DD * DD;  // alpha_w2^T
    float* wt4 = wt + 4LL * DD * DD;  // q_w
    float* wt5 = wt + 5LL * DD * DD;  // mem_w1^T
    float* wt6 = wt + 6LL * DD * DD;  // mem_w2^T

    // 2) batched xct @ {eta_w1, alpha_w1} -> tf32 gelu (sigma) -> h1[z]
    gemm_mma<1><<<grid2, 256, SMEM_GB>>>(xct, 0LL, wt0, wt1, h1, h1 + SZ,
                                         nullptr, nullptr, nullptr, nullptr,
                                         nullptr, nullptr);
    // 3) batched h1[z] @ {eta_w2, alpha_w2} -> sigmoid(xc + .) -> per-l sums
    gemm_mma<2><<<grid2, 256, SMEM_GB>>>(h1, SZ, wt2, wt3, nullptr, nullptr,
                                         xc, nullptr, nullptr, nullptr,
                                         eta_sum, alpha_sum);
    // 4) xct @ q_w^T -> hm (fp32 row-major logical)
    gemm_mma<0><<<grid1, 256, SMEM_GB>>>(xct, 0LL, wt4, wt4, hm, hm,
                                         nullptr, nullptr, nullptr, nullptr,
                                         nullptr, nullptr);
    // 5) l2norm -> q (logical), qt (tf32 sigma), qsum
    l2norm_kernel<<<MT, 128>>>(hm, qb, qt, qsum);
    // 6) parallel affine scan -> p, s
    scan_kernel<<<1, 1024>>>(eta_sum, ps);
    // 7) qt @ mem_w1 with affine+gelu epilogue -> hm (tf32 sigma), hs
    gemm_mma<3><<<grid1, 256, SMEM_GB>>>(qt, 0LL, wt5, wt5, hm, hm,
                                         nullptr, Pp, Ss, qsum,
                                         hs, nullptr);
    // 8) hm @ mem_w2 with final epilogue -> out (fp32 row-major logical)
    gemm_mma<4><<<grid1, 256, SMEM_GB>>>(hm, 0LL, wt6, wt6, out, out,
                                         qb, Pp, Ss, hs,
                                         nullptr, nullptr);
}